// round 16
// baseline (speedup 1.0000x reference)
#include <cuda_runtime.h>
#include <cstdint>

// Problem constants (fixed-shape; start_pos static = 32752)
#define NH 16
#define HD 64
#define DM 1024
#define QL 16
#define MAXLEN 32768
#define STARTPOS (MAXLEN - QL)
#define TTOT MAXLEN
#define ATTN_SCALE 0.125f
#define LOG2E 1.4426950408889634f

#define NSPLIT 32
#define WARPS_PER_BLK 2
#define NCHUNK (NSPLIT * WARPS_PER_BLK)       // 64 raw chunks (merged in pairs -> 32)
#define NMERGE NSPLIT                          // 32 merged partials per head
#define CHUNK_LEN (TTOT / NCHUNK)             // 512
#define TILE_POS 8
#define TILES_PER_CHUNK (CHUNK_LEN / TILE_POS) // 64
#define NSTAGE 4

// smem strides (floats). KSTR=72: K frag LDS.64 at (8*gq+2*tg) -> conflict-free per half-warp.
#define KSTR 72
#define VSTR 72
#define KBUF (8 * KSTR)                 // 576
#define VBUF (8 * VSTR)                 // 576
#define STAGE_F (KBUF + VBUF)           // 1152 floats
#define WARP_SMEM (NSTAGE * STAGE_F)    // 4608 floats = 18432 B

// ---------------- scratch ----------------
__device__ float g_q[NH * QL * HD];
__device__ float g_pacc[NH * NMERGE * QL * HD];   // 2 MB (merged partials)
__device__ float g_pm[NH * NMERGE * QL];
__device__ float g_pl[NH * NMERGE * QL];
__device__ float g_attn[QL * DM];

// ---------------- helpers ----------------
__device__ __forceinline__ uint32_t f2tf(float f) {
    uint32_t r;
    asm("cvt.rna.tf32.f32 %0, %1;" : "=r"(r) : "f"(f));
    return r;
}
__device__ __forceinline__ float exp2a(float x) {
    float r;
    asm("ex2.approx.f32 %0, %1;" : "=f"(r) : "f"(x));
    return r;
}
__device__ __forceinline__ void mma_tf32(float& c0, float& c1, float& c2, float& c3,
                                         const uint32_t a[4], uint32_t b0, uint32_t b1) {
    asm("mma.sync.aligned.m16n8k8.row.col.f32.tf32.tf32.f32 "
        "{%0,%1,%2,%3}, {%4,%5,%6,%7}, {%8,%9}, {%0,%1,%2,%3};"
        : "+f"(c0), "+f"(c1), "+f"(c2), "+f"(c3)
        : "r"(a[0]), "r"(a[1]), "r"(a[2]), "r"(a[3]), "r"(b0), "r"(b1));
}
__device__ __forceinline__ void cp16(uint32_t dst, const float* src) {
    asm volatile("cp.async.cg.shared.global [%0], [%1], 16;" :: "r"(dst), "l"(src));
}

// ---------------- projection kernel (known-good round-8 shape) ----------------
// mode = mode_base + blockIdx.y: 0 -> g_q (scaled), 1 -> K slot, 2 -> V slot, 3 -> d_out.
__global__ void __launch_bounds__(256) proj_kernel(
    const float* __restrict__ x_g,
    const float* __restrict__ W0,
    const float* __restrict__ W1,
    const float* __restrict__ W2,
    int mode_base,
    float* __restrict__ d_out)
{
    const int tid = threadIdx.x;
    const int warp = tid >> 5;
    const int lane = tid & 31;
    const int rq = warp & 3;
    const int oc = warp >> 2;
    const int mode = mode_base + blockIdx.y;
    const float* W = (blockIdx.y == 0) ? W0 : (blockIdx.y == 1) ? W1 : W2;
    const int obase = (blockIdx.x * 2 + oc) * 4;

    const float4* xr0 = (const float4*)(x_g + (size_t)(rq * 4 + 0) * DM) + lane;
    const float4* xr1 = (const float4*)(x_g + (size_t)(rq * 4 + 1) * DM) + lane;
    const float4* xr2 = (const float4*)(x_g + (size_t)(rq * 4 + 2) * DM) + lane;
    const float4* xr3 = (const float4*)(x_g + (size_t)(rq * 4 + 3) * DM) + lane;

    float4 wf[8];
    {
        const float4* p = (const float4*)(W + (size_t)obase * DM) + lane;
#pragma unroll
        for (int i = 0; i < 8; i++) wf[i] = __ldcs(p + 32 * i);
    }

#pragma unroll
    for (int oi = 0; oi < 4; oi++) {
        float4 wn[8];
        if (oi < 3) {
            const float4* p = (const float4*)(W + (size_t)(obase + oi + 1) * DM) + lane;
#pragma unroll
            for (int i = 0; i < 8; i++) wn[i] = __ldcs(p + 32 * i);
        }

        float a0 = 0.f, a1 = 0.f, a2 = 0.f, a3 = 0.f;
#pragma unroll
        for (int i = 0; i < 8; i++) {
            const float4 w = wf[i];
            float4 xv;
            xv = xr0[32 * i]; a0 += w.x * xv.x + w.y * xv.y + w.z * xv.z + w.w * xv.w;
            xv = xr1[32 * i]; a1 += w.x * xv.x + w.y * xv.y + w.z * xv.z + w.w * xv.w;
            xv = xr2[32 * i]; a2 += w.x * xv.x + w.y * xv.y + w.z * xv.z + w.w * xv.w;
            xv = xr3[32 * i]; a3 += w.x * xv.x + w.y * xv.y + w.z * xv.z + w.w * xv.w;
        }
#pragma unroll
        for (int off = 16; off > 0; off >>= 1) {
            a0 += __shfl_xor_sync(0xffffffffu, a0, off);
            a1 += __shfl_xor_sync(0xffffffffu, a1, off);
            a2 += __shfl_xor_sync(0xffffffffu, a2, off);
            a3 += __shfl_xor_sync(0xffffffffu, a3, off);
        }
        if (lane == 0) {
            const int o = obase + oi;
            const int r0 = rq * 4;
            if (mode == 0) {
                const int h = o >> 6, d = o & 63;
                g_q[((h * QL + r0 + 0)) * HD + d] = a0 * (ATTN_SCALE * LOG2E);
                g_q[((h * QL + r0 + 1)) * HD + d] = a1 * (ATTN_SCALE * LOG2E);
                g_q[((h * QL + r0 + 2)) * HD + d] = a2 * (ATTN_SCALE * LOG2E);
                g_q[((h * QL + r0 + 3)) * HD + d] = a3 * (ATTN_SCALE * LOG2E);
            } else if (mode == 1) {
                d_out[QL * DM + (r0 + 0) * DM + o] = a0;
                d_out[QL * DM + (r0 + 1) * DM + o] = a1;
                d_out[QL * DM + (r0 + 2) * DM + o] = a2;
                d_out[QL * DM + (r0 + 3) * DM + o] = a3;
            } else if (mode == 2) {
                d_out[2 * QL * DM + (r0 + 0) * DM + o] = a0;
                d_out[2 * QL * DM + (r0 + 1) * DM + o] = a1;
                d_out[2 * QL * DM + (r0 + 2) * DM + o] = a2;
                d_out[2 * QL * DM + (r0 + 3) * DM + o] = a3;
            } else {
                d_out[(size_t)(r0 + 0) * DM + o] = a0;
                d_out[(size_t)(r0 + 1) * DM + o] = a1;
                d_out[(size_t)(r0 + 2) * DM + o] = a2;
                d_out[(size_t)(r0 + 3) * DM + o] = a3;
            }
        }
#pragma unroll
        for (int i = 0; i < 8; i++) wf[i] = wn[i];
    }
}

// ---------------- kernel 2: split-K flash decode (round-8 mainloop + in-block pair merge) ----------------
// grid (NSPLIT, NH), block 64 (2 warps). Each warp = chunk of 512 positions; the block's
// two chunks are flash-merged in smem before writeback -> g_pacc holds 32 partials/head.
__global__ void __launch_bounds__(64) attn_kernel(
    const float* __restrict__ cache_k,
    const float* __restrict__ cache_v,
    const float* __restrict__ d_out_f)
{
    __shared__ float skv[WARPS_PER_BLK * WARP_SMEM];   // 36864 B
    __shared__ float s_m[2][QL];
    __shared__ float s_l[2][QL];
    __shared__ float s_e[2][QL];

    const int h = blockIdx.y;
    const int warp = threadIdx.x >> 5;
    const int lane = threadIdx.x & 31;
    const int chunk = blockIdx.x * WARPS_PER_BLK + warp;
    const int t_begin = chunk * CHUNK_LEN;
    const int gq = lane >> 2;
    const int tg = lane & 3;

    float* wb = skv + warp * WARP_SMEM;
    const uint32_t sbase = (uint32_t)__cvta_generic_to_shared(wb);

    const float* knew = d_out_f + QL * DM;
    const float* vnew = d_out_f + 2 * QL * DM;

    // Q fragments under the k-permutation (mirrors K's)
    const float* qh = &g_q[h * QL * HD];
    uint32_t aQ[8][4];
#pragma unroll
    for (int j = 0; j < 8; j++) {
        aQ[j][0] = f2tf(qh[gq * HD + j * 8 + 2 * tg]);
        aQ[j][1] = f2tf(qh[(gq + 8) * HD + j * 8 + 2 * tg]);
        aQ[j][2] = f2tf(qh[gq * HD + j * 8 + 2 * tg + 1]);
        aQ[j][3] = f2tf(qh[(gq + 8) * HD + j * 8 + 2 * tg + 1]);
    }

    auto load_tile = [&](int tile, int buf) {
        const int t0 = t_begin + tile * TILE_POS;
        const bool isnew = (t0 >= STARTPOS);
        const float* kb = isnew ? (knew + (size_t)(t0 - STARTPOS) * DM + h * HD)
                                : (cache_k + (size_t)t0 * DM + h * HD);
        const float* vb = isnew ? (vnew + (size_t)(t0 - STARTPOS) * DM + h * HD)
                                : (cache_v + (size_t)t0 * DM + h * HD);
        const uint32_t kd = sbase + buf * (STAGE_F * 4);
        const uint32_t vd = kd + KBUF * 4;
#pragma unroll
        for (int i = 0; i < 4; i++) {
            const int c = lane + 32 * i;
            const int row = c >> 4;
            const int colf = (c & 15) * 4;
            cp16(kd + (row * KSTR + colf) * 4, kb + (size_t)row * DM + colf);
            cp16(vd + (row * VSTR + colf) * 4, vb + (size_t)row * DM + colf);
        }
        asm volatile("cp.async.commit_group;");
    };

    float m0 = -1e30f, m1 = -1e30f, l0 = 0.f, l1 = 0.f;
    float o[8][4];
#pragma unroll
    for (int n = 0; n < 8; n++) { o[n][0] = 0.f; o[n][1] = 0.f; o[n][2] = 0.f; o[n][3] = 0.f; }

    load_tile(0, 0);
    load_tile(1, 1);
    load_tile(2, 2);

#pragma unroll 1
    for (int tile = 0; tile < TILES_PER_CHUNK; tile++) {
        if (tile + 3 < TILES_PER_CHUNK) {
            load_tile(tile + 3, (tile + 3) & 3);
            asm volatile("cp.async.wait_group 3;");
        } else if (tile + 3 == TILES_PER_CHUNK) {
            asm volatile("cp.async.wait_group 2;");
        } else if (tile + 2 == TILES_PER_CHUNK) {
            asm volatile("cp.async.wait_group 1;");
        } else {
            asm volatile("cp.async.wait_group 0;");
        }
        __syncwarp();

        const float* sk = wb + (tile & 3) * STAGE_F;
        const float* sv = sk + KBUF;

        uint32_t bK[8][2];
#pragma unroll
        for (int j = 0; j < 8; j++) {
            const float2 kv = *(const float2*)(sk + gq * KSTR + j * 8 + 2 * tg);
            bK[j][0] = f2tf(kv.x);
            bK[j][1] = f2tf(kv.y);
        }

        float c0 = 0.f, c1 = 0.f, c2 = 0.f, c3 = 0.f;
#pragma unroll
        for (int j = 0; j < 8; j++) mma_tf32(c0, c1, c2, c3, aQ[j], bK[j][0], bK[j][1]);

        const int t0 = t_begin + tile * TILE_POS;
        if (t0 >= STARTPOS) {
            const int ibase = t0 - STARTPOS;
            if (ibase + 2 * tg     > gq)     c0 = -1e30f;
            if (ibase + 2 * tg + 1 > gq)     c1 = -1e30f;
            if (ibase + 2 * tg     > gq + 8) c2 = -1e30f;
            if (ibase + 2 * tg + 1 > gq + 8) c3 = -1e30f;
        }

        float tm0 = fmaxf(c0, c1), tm1 = fmaxf(c2, c3);
        tm0 = fmaxf(tm0, __shfl_xor_sync(0xffffffffu, tm0, 1));
        tm0 = fmaxf(tm0, __shfl_xor_sync(0xffffffffu, tm0, 2));
        tm1 = fmaxf(tm1, __shfl_xor_sync(0xffffffffu, tm1, 1));
        tm1 = fmaxf(tm1, __shfl_xor_sync(0xffffffffu, tm1, 2));
        const float nm0 = fmaxf(m0, tm0), nm1 = fmaxf(m1, tm1);
        const float al0 = exp2a(m0 - nm0), al1 = exp2a(m1 - nm1);
        m0 = nm0; m1 = nm1;
        const float p0 = exp2a(c0 - nm0), p1 = exp2a(c1 - nm0);
        const float p2 = exp2a(c2 - nm1), p3 = exp2a(c3 - nm1);
        l0 = l0 * al0 + p0 + p1;
        l1 = l1 * al1 + p2 + p3;
        if (al0 != 1.f) {
#pragma unroll
            for (int n = 0; n < 8; n++) { o[n][0] *= al0; o[n][1] *= al0; }
        }
        if (al1 != 1.f) {
#pragma unroll
            for (int n = 0; n < 8; n++) { o[n][2] *= al1; o[n][3] *= al1; }
        }

        const int srcA = (lane & ~3) + (tg >> 1);
        const int srcB = srcA + 2;
        const float u00 = __shfl_sync(0xffffffffu, p0, srcA);
        const float u01 = __shfl_sync(0xffffffffu, p1, srcA);
        const float u10 = __shfl_sync(0xffffffffu, p0, srcB);
        const float u11 = __shfl_sync(0xffffffffu, p1, srcB);
        const float u20 = __shfl_sync(0xffffffffu, p2, srcA);
        const float u21 = __shfl_sync(0xffffffffu, p3, srcA);
        const float u30 = __shfl_sync(0xffffffffu, p2, srcB);
        const float u31 = __shfl_sync(0xffffffffu, p3, srcB);
        const bool oddq = (tg & 1);
        uint32_t aP[4];
        aP[0] = f2tf(oddq ? u01 : u00);
        aP[1] = f2tf(oddq ? u21 : u20);
        aP[2] = f2tf(oddq ? u11 : u10);
        aP[3] = f2tf(oddq ? u31 : u30);

#pragma unroll
        for (int n = 0; n < 8; n++) {
            const uint32_t bv0 = f2tf(sv[tg * VSTR + n * 8 + gq]);
            const uint32_t bv1 = f2tf(sv[(tg + 4) * VSTR + n * 8 + gq]);
            mma_tf32(o[n][0], o[n][1], o[n][2], o[n][3], aP, bv0, bv1);
        }
    }

    l0 += __shfl_xor_sync(0xffffffffu, l0, 1);
    l0 += __shfl_xor_sync(0xffffffffu, l0, 2);
    l1 += __shfl_xor_sync(0xffffffffu, l1, 1);
    l1 += __shfl_xor_sync(0xffffffffu, l1, 2);

    // ---- stage per-warp O tile (stride 68) + per-row stats ----
    float* st = wb;
#pragma unroll
    for (int n = 0; n < 8; n++) {
        st[gq * 68 + n * 8 + 2 * tg]           = o[n][0];
        st[gq * 68 + n * 8 + 2 * tg + 1]       = o[n][1];
        st[(gq + 8) * 68 + n * 8 + 2 * tg]     = o[n][2];
        st[(gq + 8) * 68 + n * 8 + 2 * tg + 1] = o[n][3];
    }
    if (tg == 0) {
        s_m[warp][gq] = m0;
        s_m[warp][gq + 8] = m1;
        s_l[warp][gq] = l0;
        s_l[warp][gq + 8] = l1;
    }
    __syncthreads();

    // ---- in-block flash merge of the two chunks ----
    if (threadIdx.x < QL) {
        const int r = threadIdx.x;
        const float M = fmaxf(s_m[0][r], s_m[1][r]);
        const float e0 = exp2a(s_m[0][r] - M);
        const float e1 = exp2a(s_m[1][r] - M);
        s_e[0][r] = e0;
        s_e[1][r] = e1;
        const int base = (h * NMERGE + blockIdx.x) * QL;
        g_pm[base + r] = M;
        g_pl[base + r] = s_l[0][r] * e0 + s_l[1][r] * e1;
    }
    __syncthreads();

    const float* st0 = skv;
    const float* st1 = skv + WARP_SMEM;
    float4* pa = (float4*)&g_pacc[(size_t)(h * NMERGE + blockIdx.x) * QL * HD];
#pragma unroll
    for (int i = 0; i < 4; i++) {
        const int idx = i * 64 + threadIdx.x;
        const int r = idx >> 4, d4 = idx & 15;
        const float4 v0 = *(const float4*)(st0 + r * 68 + d4 * 4);
        const float4 v1 = *(const float4*)(st1 + r * 68 + d4 * 4);
        const float e0 = s_e[0][r], e1 = s_e[1][r];
        float4 mo;
        mo.x = v0.x * e0 + v1.x * e1;
        mo.y = v0.y * e0 + v1.y * e1;
        mo.z = v0.z * e0 + v1.z * e1;
        mo.w = v0.w * e0 + v1.w * e1;
        pa[idx] = mo;
    }
}

// ---------------- kernel 3: combine 32 merged partials ----------------
// grid (QL, NH), block 256 = 16 d4-cols x 16 groups of 2 partials
__global__ void __launch_bounds__(256) reduce_kernel()
{
    const int r = blockIdx.x;
    const int h = blockIdx.y;
    const int tid = threadIdx.x;

    __shared__ float sm[NMERGE];
    __shared__ float ss[NMERGE];
    __shared__ float sl[NMERGE];
    __shared__ float4 sp[16][16];

    float mw = 0.f, lw = 0.f;
    if (tid < NMERGE) {
        mw = g_pm[(h * NMERGE + tid) * QL + r];
        lw = g_pl[(h * NMERGE + tid) * QL + r];
        sm[tid] = mw;
    }
    __syncthreads();
#pragma unroll
    for (int s = 16; s > 0; s >>= 1) {
        if (tid < s) sm[tid] = fmaxf(sm[tid], sm[tid + s]);
        __syncthreads();
    }
    const float M = sm[0];
    if (tid < NMERGE) {
        const float sc = exp2a(mw - M);
        ss[tid] = sc;
        sl[tid] = lw * sc;
    }
    __syncthreads();
#pragma unroll
    for (int s = 16; s > 0; s >>= 1) {
        if (tid < s) sl[tid] += sl[tid + s];
        __syncthreads();
    }

    const int d4 = tid & 15;
    const int wg = tid >> 4;
    const float4* bp = (const float4*)
        (g_pacc + ((size_t)(h * NMERGE + wg * 2) * QL + r) * HD) + d4;
    float4 a = make_float4(0.f, 0.f, 0.f, 0.f);
#pragma unroll
    for (int j = 0; j < 2; j++) {
        const float4 v = bp[(size_t)j * QL * HD / 4];
        const float s = ss[wg * 2 + j];
        a.x += v.x * s; a.y += v.y * s; a.z += v.z * s; a.w += v.w * s;
    }
    sp[wg][d4] = a;
    __syncthreads();
#pragma unroll
    for (int s = 8; s > 0; s >>= 1) {
        if (wg < s) {
            float4 b = sp[wg + s][d4];
            float4 c = sp[wg][d4];
            c.x += b.x; c.y += b.y; c.z += b.z; c.w += b.w;
            sp[wg][d4] = c;
        }
        __syncthreads();
    }
    if (tid < 16) {
        const float inv = 1.f / sl[0];
        float4 c = sp[0][tid];
        c.x *= inv; c.y *= inv; c.z *= inv; c.w *= inv;
        *((float4*)(g_attn + r * DM + h * HD) + tid) = c;
    }
}

// ---------------- launch ----------------
extern "C" void kernel_launch(void* const* d_in, const int* in_sizes, int n_in,
                              void* d_out, int out_size)
{
    const float* query = (const float*)d_in[0];
    const float* Wq    = (const float*)d_in[1];
    const float* Wk    = (const float*)d_in[2];
    const float* Wv    = (const float*)d_in[3];
    const float* Wo    = (const float*)d_in[4];
    const float* ck    = (const float*)d_in[5];
    const float* cv    = (const float*)d_in[6];
    float* out = (float*)d_out;

    static float* g_attn_ptr = nullptr;
    if (!g_attn_ptr) cudaGetSymbolAddress((void**)&g_attn_ptr, g_attn);

    proj_kernel<<<dim3(128, 3), 256>>>(query, Wq, Wk, Wv, 0, out);
    attn_kernel<<<dim3(NSPLIT, NH), 64>>>(ck, cv, out);
    reduce_kernel<<<dim3(QL, NH), 256>>>();
    proj_kernel<<<dim3(128, 1), 256>>>(g_attn_ptr, Wo, Wo, Wo, 3, out);
}

// round 17
// speedup vs baseline: 1.3399x; 1.3399x over previous
#include <cuda_runtime.h>
#include <cstdint>

// Problem constants (fixed-shape; start_pos static = 32752)
#define NH 16
#define HD 64
#define DM 1024
#define QL 16
#define MAXLEN 32768
#define STARTPOS (MAXLEN - QL)
#define TTOT MAXLEN
#define ATTN_SCALE 0.125f
#define LOG2E 1.4426950408889634f

#define NSPLIT 32
#define WARPS_PER_BLK 2
#define NCHUNK (NSPLIT * WARPS_PER_BLK)       // 64 raw chunks (merged in pairs -> 32)
#define NMERGE NSPLIT                          // 32 merged partials per head
#define CHUNK_LEN (TTOT / NCHUNK)             // 512
#define TILE_POS 8
#define TILES_PER_CHUNK (CHUNK_LEN / TILE_POS) // 64
#define NSTAGE 4

// smem strides (floats). KSTR=72: K frag LDS.64 at (8*gq+2*tg) -> conflict-free per half-warp.
#define KSTR 72
#define VSTR 72
#define KBUF (8 * KSTR)                 // 576
#define VBUF (8 * VSTR)                 // 576
#define STAGE_F (KBUF + VBUF)           // 1152 floats
#define WARP_SMEM (NSTAGE * STAGE_F)    // 4608 floats = 18432 B

// ---------------- scratch ----------------
__device__ float g_q[NH * QL * HD];
__device__ float g_pacc[NH * NMERGE * QL * HD];   // 2 MB (merged partials)
__device__ float g_pm[NH * NMERGE * QL];
__device__ float g_pl[NH * NMERGE * QL];
__device__ float g_attn[QL * DM];

// ---------------- helpers ----------------
__device__ __forceinline__ uint32_t f2tf(float f) {
    uint32_t r;
    asm("cvt.rna.tf32.f32 %0, %1;" : "=r"(r) : "f"(f));
    return r;
}
__device__ __forceinline__ float exp2a(float x) {
    float r;
    asm("ex2.approx.f32 %0, %1;" : "=f"(r) : "f"(x));
    return r;
}
__device__ __forceinline__ void mma_tf32(float& c0, float& c1, float& c2, float& c3,
                                         const uint32_t a[4], uint32_t b0, uint32_t b1) {
    asm("mma.sync.aligned.m16n8k8.row.col.f32.tf32.tf32.f32 "
        "{%0,%1,%2,%3}, {%4,%5,%6,%7}, {%8,%9}, {%0,%1,%2,%3};"
        : "+f"(c0), "+f"(c1), "+f"(c2), "+f"(c3)
        : "r"(a[0]), "r"(a[1]), "r"(a[2]), "r"(a[3]), "r"(b0), "r"(b1));
}
__device__ __forceinline__ void cp16(uint32_t dst, const float* src) {
    asm volatile("cp.async.cg.shared.global [%0], [%1], 16;" :: "r"(dst), "l"(src));
}

// ---------------- projection kernel (known-good round-8 shape) ----------------
// mode = mode_base + blockIdx.y: 0 -> g_q (scaled), 1 -> K slot, 2 -> V slot, 3 -> d_out.
__global__ void __launch_bounds__(256) proj_kernel(
    const float* __restrict__ x_g,
    const float* __restrict__ W0,
    const float* __restrict__ W1,
    const float* __restrict__ W2,
    int mode_base,
    float* __restrict__ d_out)
{
    const int tid = threadIdx.x;
    const int warp = tid >> 5;
    const int lane = tid & 31;
    const int rq = warp & 3;
    const int oc = warp >> 2;
    const int mode = mode_base + blockIdx.y;
    const float* W = (blockIdx.y == 0) ? W0 : (blockIdx.y == 1) ? W1 : W2;
    const int obase = (blockIdx.x * 2 + oc) * 4;

    const float4* xr0 = (const float4*)(x_g + (size_t)(rq * 4 + 0) * DM) + lane;
    const float4* xr1 = (const float4*)(x_g + (size_t)(rq * 4 + 1) * DM) + lane;
    const float4* xr2 = (const float4*)(x_g + (size_t)(rq * 4 + 2) * DM) + lane;
    const float4* xr3 = (const float4*)(x_g + (size_t)(rq * 4 + 3) * DM) + lane;

    float4 wf[8];
    {
        const float4* p = (const float4*)(W + (size_t)obase * DM) + lane;
#pragma unroll
        for (int i = 0; i < 8; i++) wf[i] = __ldcs(p + 32 * i);
    }

#pragma unroll
    for (int oi = 0; oi < 4; oi++) {
        float4 wn[8];
        if (oi < 3) {
            const float4* p = (const float4*)(W + (size_t)(obase + oi + 1) * DM) + lane;
#pragma unroll
            for (int i = 0; i < 8; i++) wn[i] = __ldcs(p + 32 * i);
        }

        float a0 = 0.f, a1 = 0.f, a2 = 0.f, a3 = 0.f;
#pragma unroll
        for (int i = 0; i < 8; i++) {
            const float4 w = wf[i];
            float4 xv;
            xv = xr0[32 * i]; a0 += w.x * xv.x + w.y * xv.y + w.z * xv.z + w.w * xv.w;
            xv = xr1[32 * i]; a1 += w.x * xv.x + w.y * xv.y + w.z * xv.z + w.w * xv.w;
            xv = xr2[32 * i]; a2 += w.x * xv.x + w.y * xv.y + w.z * xv.z + w.w * xv.w;
            xv = xr3[32 * i]; a3 += w.x * xv.x + w.y * xv.y + w.z * xv.z + w.w * xv.w;
        }
#pragma unroll
        for (int off = 16; off > 0; off >>= 1) {
            a0 += __shfl_xor_sync(0xffffffffu, a0, off);
            a1 += __shfl_xor_sync(0xffffffffu, a1, off);
            a2 += __shfl_xor_sync(0xffffffffu, a2, off);
            a3 += __shfl_xor_sync(0xffffffffu, a3, off);
        }
        if (lane == 0) {
            const int o = obase + oi;
            const int r0 = rq * 4;
            if (mode == 0) {
                const int h = o >> 6, d = o & 63;
                g_q[((h * QL + r0 + 0)) * HD + d] = a0 * (ATTN_SCALE * LOG2E);
                g_q[((h * QL + r0 + 1)) * HD + d] = a1 * (ATTN_SCALE * LOG2E);
                g_q[((h * QL + r0 + 2)) * HD + d] = a2 * (ATTN_SCALE * LOG2E);
                g_q[((h * QL + r0 + 3)) * HD + d] = a3 * (ATTN_SCALE * LOG2E);
            } else if (mode == 1) {
                d_out[QL * DM + (r0 + 0) * DM + o] = a0;
                d_out[QL * DM + (r0 + 1) * DM + o] = a1;
                d_out[QL * DM + (r0 + 2) * DM + o] = a2;
                d_out[QL * DM + (r0 + 3) * DM + o] = a3;
            } else if (mode == 2) {
                d_out[2 * QL * DM + (r0 + 0) * DM + o] = a0;
                d_out[2 * QL * DM + (r0 + 1) * DM + o] = a1;
                d_out[2 * QL * DM + (r0 + 2) * DM + o] = a2;
                d_out[2 * QL * DM + (r0 + 3) * DM + o] = a3;
            } else {
                d_out[(size_t)(r0 + 0) * DM + o] = a0;
                d_out[(size_t)(r0 + 1) * DM + o] = a1;
                d_out[(size_t)(r0 + 2) * DM + o] = a2;
                d_out[(size_t)(r0 + 3) * DM + o] = a3;
            }
        }
#pragma unroll
        for (int i = 0; i < 8; i++) wf[i] = wn[i];
    }
}

// ---------------- kernel 2: split-K flash decode (round-8 mainloop + in-block pair merge) ----------------
// grid (NSPLIT, NH), block 64 (2 warps). Each warp = chunk of 512 positions; the block's
// two chunks are flash-merged in smem before writeback -> g_pacc holds 32 partials/head.
__global__ void __launch_bounds__(64) attn_kernel(
    const float* __restrict__ cache_k,
    const float* __restrict__ cache_v,
    const float* __restrict__ d_out_f)
{
    __shared__ float skv[WARPS_PER_BLK * WARP_SMEM];   // 36864 B
    __shared__ float s_m[2][QL];
    __shared__ float s_l[2][QL];
    __shared__ float s_e[2][QL];

    const int h = blockIdx.y;
    const int warp = threadIdx.x >> 5;
    const int lane = threadIdx.x & 31;
    const int chunk = blockIdx.x * WARPS_PER_BLK + warp;
    const int t_begin = chunk * CHUNK_LEN;
    const int gq = lane >> 2;
    const int tg = lane & 3;

    float* wb = skv + warp * WARP_SMEM;
    const uint32_t sbase = (uint32_t)__cvta_generic_to_shared(wb);

    const float* knew = d_out_f + QL * DM;
    const float* vnew = d_out_f + 2 * QL * DM;

    // Q fragments under the k-permutation (mirrors K's)
    const float* qh = &g_q[h * QL * HD];
    uint32_t aQ[8][4];
#pragma unroll
    for (int j = 0; j < 8; j++) {
        aQ[j][0] = f2tf(qh[gq * HD + j * 8 + 2 * tg]);
        aQ[j][1] = f2tf(qh[(gq + 8) * HD + j * 8 + 2 * tg]);
        aQ[j][2] = f2tf(qh[gq * HD + j * 8 + 2 * tg + 1]);
        aQ[j][3] = f2tf(qh[(gq + 8) * HD + j * 8 + 2 * tg + 1]);
    }

    auto load_tile = [&](int tile, int buf) {
        const int t0 = t_begin + tile * TILE_POS;
        const bool isnew = (t0 >= STARTPOS);
        const float* kb = isnew ? (knew + (size_t)(t0 - STARTPOS) * DM + h * HD)
                                : (cache_k + (size_t)t0 * DM + h * HD);
        const float* vb = isnew ? (vnew + (size_t)(t0 - STARTPOS) * DM + h * HD)
                                : (cache_v + (size_t)t0 * DM + h * HD);
        const uint32_t kd = sbase + buf * (STAGE_F * 4);
        const uint32_t vd = kd + KBUF * 4;
#pragma unroll
        for (int i = 0; i < 4; i++) {
            const int c = lane + 32 * i;
            const int row = c >> 4;
            const int colf = (c & 15) * 4;
            cp16(kd + (row * KSTR + colf) * 4, kb + (size_t)row * DM + colf);
            cp16(vd + (row * VSTR + colf) * 4, vb + (size_t)row * DM + colf);
        }
        asm volatile("cp.async.commit_group;");
    };

    float m0 = -1e30f, m1 = -1e30f, l0 = 0.f, l1 = 0.f;
    float o[8][4];
#pragma unroll
    for (int n = 0; n < 8; n++) { o[n][0] = 0.f; o[n][1] = 0.f; o[n][2] = 0.f; o[n][3] = 0.f; }

    load_tile(0, 0);
    load_tile(1, 1);
    load_tile(2, 2);

#pragma unroll 1
    for (int tile = 0; tile < TILES_PER_CHUNK; tile++) {
        if (tile + 3 < TILES_PER_CHUNK) {
            load_tile(tile + 3, (tile + 3) & 3);
            asm volatile("cp.async.wait_group 3;");
        } else if (tile + 3 == TILES_PER_CHUNK) {
            asm volatile("cp.async.wait_group 2;");
        } else if (tile + 2 == TILES_PER_CHUNK) {
            asm volatile("cp.async.wait_group 1;");
        } else {
            asm volatile("cp.async.wait_group 0;");
        }
        __syncwarp();

        const float* sk = wb + (tile & 3) * STAGE_F;
        const float* sv = sk + KBUF;

        uint32_t bK[8][2];
#pragma unroll
        for (int j = 0; j < 8; j++) {
            const float2 kv = *(const float2*)(sk + gq * KSTR + j * 8 + 2 * tg);
            bK[j][0] = f2tf(kv.x);
            bK[j][1] = f2tf(kv.y);
        }

        float c0 = 0.f, c1 = 0.f, c2 = 0.f, c3 = 0.f;
#pragma unroll
        for (int j = 0; j < 8; j++) mma_tf32(c0, c1, c2, c3, aQ[j], bK[j][0], bK[j][1]);

        const int t0 = t_begin + tile * TILE_POS;
        if (t0 >= STARTPOS) {
            const int ibase = t0 - STARTPOS;
            if (ibase + 2 * tg     > gq)     c0 = -1e30f;
            if (ibase + 2 * tg + 1 > gq)     c1 = -1e30f;
            if (ibase + 2 * tg     > gq + 8) c2 = -1e30f;
            if (ibase + 2 * tg + 1 > gq + 8) c3 = -1e30f;
        }

        float tm0 = fmaxf(c0, c1), tm1 = fmaxf(c2, c3);
        tm0 = fmaxf(tm0, __shfl_xor_sync(0xffffffffu, tm0, 1));
        tm0 = fmaxf(tm0, __shfl_xor_sync(0xffffffffu, tm0, 2));
        tm1 = fmaxf(tm1, __shfl_xor_sync(0xffffffffu, tm1, 1));
        tm1 = fmaxf(tm1, __shfl_xor_sync(0xffffffffu, tm1, 2));
        const float nm0 = fmaxf(m0, tm0), nm1 = fmaxf(m1, tm1);
        const float al0 = exp2a(m0 - nm0), al1 = exp2a(m1 - nm1);
        m0 = nm0; m1 = nm1;
        const float p0 = exp2a(c0 - nm0), p1 = exp2a(c1 - nm0);
        const float p2 = exp2a(c2 - nm1), p3 = exp2a(c3 - nm1);
        l0 = l0 * al0 + p0 + p1;
        l1 = l1 * al1 + p2 + p3;
        if (al0 != 1.f) {
#pragma unroll
            for (int n = 0; n < 8; n++) { o[n][0] *= al0; o[n][1] *= al0; }
        }
        if (al1 != 1.f) {
#pragma unroll
            for (int n = 0; n < 8; n++) { o[n][2] *= al1; o[n][3] *= al1; }
        }

        const int srcA = (lane & ~3) + (tg >> 1);
        const int srcB = srcA + 2;
        const float u00 = __shfl_sync(0xffffffffu, p0, srcA);
        const float u01 = __shfl_sync(0xffffffffu, p1, srcA);
        const float u10 = __shfl_sync(0xffffffffu, p0, srcB);
        const float u11 = __shfl_sync(0xffffffffu, p1, srcB);
        const float u20 = __shfl_sync(0xffffffffu, p2, srcA);
        const float u21 = __shfl_sync(0xffffffffu, p3, srcA);
        const float u30 = __shfl_sync(0xffffffffu, p2, srcB);
        const float u31 = __shfl_sync(0xffffffffu, p3, srcB);
        const bool oddq = (tg & 1);
        uint32_t aP[4];
        aP[0] = f2tf(oddq ? u01 : u00);
        aP[1] = f2tf(oddq ? u21 : u20);
        aP[2] = f2tf(oddq ? u11 : u10);
        aP[3] = f2tf(oddq ? u31 : u30);

#pragma unroll
        for (int n = 0; n < 8; n++) {
            const uint32_t bv0 = f2tf(sv[tg * VSTR + n * 8 + gq]);
            const uint32_t bv1 = f2tf(sv[(tg + 4) * VSTR + n * 8 + gq]);
            mma_tf32(o[n][0], o[n][1], o[n][2], o[n][3], aP, bv0, bv1);
        }
    }

    l0 += __shfl_xor_sync(0xffffffffu, l0, 1);
    l0 += __shfl_xor_sync(0xffffffffu, l0, 2);
    l1 += __shfl_xor_sync(0xffffffffu, l1, 1);
    l1 += __shfl_xor_sync(0xffffffffu, l1, 2);

    // ---- stage per-warp O tile (stride 68) + per-row stats ----
    float* st = wb;
#pragma unroll
    for (int n = 0; n < 8; n++) {
        st[gq * 68 + n * 8 + 2 * tg]           = o[n][0];
        st[gq * 68 + n * 8 + 2 * tg + 1]       = o[n][1];
        st[(gq + 8) * 68 + n * 8 + 2 * tg]     = o[n][2];
        st[(gq + 8) * 68 + n * 8 + 2 * tg + 1] = o[n][3];
    }
    if (tg == 0) {
        s_m[warp][gq] = m0;
        s_m[warp][gq + 8] = m1;
        s_l[warp][gq] = l0;
        s_l[warp][gq + 8] = l1;
    }
    __syncthreads();

    // ---- in-block flash merge of the two chunks ----
    if (threadIdx.x < QL) {
        const int r = threadIdx.x;
        const float M = fmaxf(s_m[0][r], s_m[1][r]);
        const float e0 = exp2a(s_m[0][r] - M);
        const float e1 = exp2a(s_m[1][r] - M);
        s_e[0][r] = e0;
        s_e[1][r] = e1;
        const int base = (h * NMERGE + blockIdx.x) * QL;
        g_pm[base + r] = M;
        g_pl[base + r] = s_l[0][r] * e0 + s_l[1][r] * e1;
    }
    __syncthreads();

    const float* st0 = skv;
    const float* st1 = skv + WARP_SMEM;
    float4* pa = (float4*)&g_pacc[(size_t)(h * NMERGE + blockIdx.x) * QL * HD];
#pragma unroll
    for (int i = 0; i < 4; i++) {
        const int idx = i * 64 + threadIdx.x;
        const int r = idx >> 4, d4 = idx & 15;
        const float4 v0 = *(const float4*)(st0 + r * 68 + d4 * 4);
        const float4 v1 = *(const float4*)(st1 + r * 68 + d4 * 4);
        const float e0 = s_e[0][r], e1 = s_e[1][r];
        float4 mo;
        mo.x = v0.x * e0 + v1.x * e1;
        mo.y = v0.y * e0 + v1.y * e1;
        mo.z = v0.z * e0 + v1.z * e1;
        mo.w = v0.w * e0 + v1.w * e1;
        pa[idx] = mo;
    }
}

// ---------------- kernel 3: combine 32 merged partials ----------------
// grid (QL, NH), block 256 = 16 d4-cols x 16 groups of 2 partials
__global__ void __launch_bounds__(256) reduce_kernel()
{
    const int r = blockIdx.x;
    const int h = blockIdx.y;
    const int tid = threadIdx.x;

    __shared__ float sm[NMERGE];
    __shared__ float ss[NMERGE];
    __shared__ float sl[NMERGE];
    __shared__ float4 sp[16][16];

    float mw = 0.f, lw = 0.f;
    if (tid < NMERGE) {
        mw = g_pm[(h * NMERGE + tid) * QL + r];
        lw = g_pl[(h * NMERGE + tid) * QL + r];
        sm[tid] = mw;
    }
    __syncthreads();
#pragma unroll
    for (int s = 16; s > 0; s >>= 1) {
        if (tid < s) sm[tid] = fmaxf(sm[tid], sm[tid + s]);
        __syncthreads();
    }
    const float M = sm[0];
    if (tid < NMERGE) {
        const float sc = exp2a(mw - M);
        ss[tid] = sc;
        sl[tid] = lw * sc;
    }
    __syncthreads();
#pragma unroll
    for (int s = 16; s > 0; s >>= 1) {
        if (tid < s) sl[tid] += sl[tid + s];
        __syncthreads();
    }

    const int d4 = tid & 15;
    const int wg = tid >> 4;
    const float4* bp = (const float4*)
        (g_pacc + ((size_t)(h * NMERGE + wg * 2) * QL + r) * HD) + d4;
    float4 a = make_float4(0.f, 0.f, 0.f, 0.f);
#pragma unroll
    for (int j = 0; j < 2; j++) {
        const float4 v = bp[(size_t)j * QL * HD / 4];
        const float s = ss[wg * 2 + j];
        a.x += v.x * s; a.y += v.y * s; a.z += v.z * s; a.w += v.w * s;
    }
    sp[wg][d4] = a;
    __syncthreads();
#pragma unroll
    for (int s = 8; s > 0; s >>= 1) {
        if (wg < s) {
            float4 b = sp[wg + s][d4];
            float4 c = sp[wg][d4];
            c.x += b.x; c.y += b.y; c.z += b.z; c.w += b.w;
            sp[wg][d4] = c;
        }
        __syncthreads();
    }
    if (tid < 16) {
        const float inv = 1.f / sl[0];
        float4 c = sp[0][tid];
        c.x *= inv; c.y *= inv; c.z *= inv; c.w *= inv;
        *((float4*)(g_attn + r * DM + h * HD) + tid) = c;
    }
}

// ---------------- launch ----------------
extern "C" void kernel_launch(void* const* d_in, const int* in_sizes, int n_in,
                              void* d_out, int out_size)
{
    const float* query = (const float*)d_in[0];
    const float* Wq    = (const float*)d_in[1];
    const float* Wk    = (const float*)d_in[2];
    const float* Wv    = (const float*)d_in[3];
    const float* Wo    = (const float*)d_in[4];
    const float* ck    = (const float*)d_in[5];
    const float* cv    = (const float*)d_in[6];
    float* out = (float*)d_out;

    static float* g_attn_ptr = nullptr;
    if (!g_attn_ptr) cudaGetSymbolAddress((void**)&g_attn_ptr, g_attn);

    proj_kernel<<<dim3(128, 3), 256>>>(query, Wq, Wk, Wv, 0, out);
    attn_kernel<<<dim3(NSPLIT, NH), 64>>>(ck, cv, out);
    reduce_kernel<<<dim3(QL, NH), 256>>>();
    proj_kernel<<<dim3(128, 1), 256>>>(g_attn_ptr, Wo, Wo, Wo, 3, out);
}